// round 2
// baseline (speedup 1.0000x reference)
#include <cuda_runtime.h>
#include <cuda_bf16.h>
#include <cstdint>

#define BB 16
#define NN 4096

// ---------------- scratch (device globals; no allocation allowed) ----------
__device__ float g_dis[BB * NN];                       // 256 KB
__device__ float g_zT[(size_t)BB * 64 * NN];           // 16 MB  (tf32 bits), [b][d][m]
__device__ float g_h [(size_t)BB * NN * 64];           // 16 MB  layer output [b][n][d]
__device__ float g_pool[BB * 32 * 128];                // partial pooling

// ---------------- 1) degree / dis kernel -----------------------------------
__global__ void deg_kernel(const float* __restrict__ adj) {
    int row = blockIdx.x;                               // 0..BB*NN-1
    const float4* p = reinterpret_cast<const float4*>(adj + (size_t)row * NN);
    float s = 0.f;
#pragma unroll
    for (int i = 0; i < 8; i++) {
        float4 v = p[threadIdx.x + i * 128];
        s += (v.x + v.y) + (v.z + v.w);
    }
#pragma unroll
    for (int o = 16; o; o >>= 1) s += __shfl_xor_sync(0xffffffffu, s, o);
    __shared__ float ws[4];
    if ((threadIdx.x & 31) == 0) ws[threadIdx.x >> 5] = s;
    __syncthreads();
    if (threadIdx.x == 0) {
        float t = ws[0] + ws[1] + ws[2] + ws[3];
        g_dis[row] = rsqrtf(fmaxf(t, 1.0f));
    }
}

// ---------------- 2) projection kernels: z = dis * (x @ W), stored tf32, T --
// use_h == 0: x = concat(type_emb[nt], label_emb[nl]);  use_h == 1: x = g_h row
__global__ void proj_kernel(const int* __restrict__ ntypes,
                            const int* __restrict__ nlabels,
                            const float* __restrict__ type_emb,
                            const float* __restrict__ label_emb,
                            int use_h,
                            const float* __restrict__ W) {
    __shared__ float Ws[64 * 64];
    __shared__ float zs[64 * 33];
    int tid = threadIdx.x;
    for (int i = tid; i < 4096; i += 256) Ws[i] = W[i];
    __syncthreads();

    int base = blockIdx.x * 32;                         // 32 nodes per block
    int w = tid >> 5, lane = tid & 31;

    for (int i = 0; i < 4; i++) {
        int node = base + w * 4 + i;                    // global node (b*N + n)
        float xlo, xhi;
        if (use_h) {
            xlo = g_h[(size_t)node * 64 + lane];
            xhi = g_h[(size_t)node * 64 + 32 + lane];
        } else {
            int nt = ntypes[node], nl = nlabels[node];
            xlo = type_emb[nt * 32 + lane];
            xhi = label_emb[nl * 32 + lane];
        }
        float a0 = 0.f, a1 = 0.f;
#pragma unroll
        for (int k = 0; k < 32; k++) {
            float xk = __shfl_sync(0xffffffffu, xlo, k);
            a0 += xk * Ws[k * 64 + lane];
            a1 += xk * Ws[k * 64 + 32 + lane];
        }
#pragma unroll
        for (int k = 0; k < 32; k++) {
            float xk = __shfl_sync(0xffffffffu, xhi, k);
            a0 += xk * Ws[(k + 32) * 64 + lane];
            a1 += xk * Ws[(k + 32) * 64 + 32 + lane];
        }
        float dm = g_dis[node];
        a0 *= dm; a1 *= dm;
        uint32_t u0, u1;
        asm("cvt.rna.tf32.f32 %0, %1;" : "=r"(u0) : "f"(a0));
        asm("cvt.rna.tf32.f32 %0, %1;" : "=r"(u1) : "f"(a1));
        int mm = w * 4 + i;
        zs[lane * 33 + mm]        = __uint_as_float(u0);
        zs[(lane + 32) * 33 + mm] = __uint_as_float(u1);
    }
    __syncthreads();

    int b  = base >> 12;
    int ml = base & 4095;
#pragma unroll
    for (int j = 0; j < 8; j++) {
        int li = tid + j * 256;
        int d = li >> 5, mm = li & 31;
        g_zT[((size_t)b * 64 + d) * NN + ml + mm] = zs[d * 33 + mm];
    }
}

// ---------------- 3) big GEMM: h = relu(dis_n * (adj @ zT^T) + bias) --------
// CTA tile 128(M) x 64(N), K chunks of 32, cp.async double buffer, tf32 HMMA.
__global__ void __launch_bounds__(256, 2)
gcn_gemm(const float* __restrict__ adj, const float* __restrict__ bias) {
    extern __shared__ float smem[];                     // As[2][128][32] + Bs[2][64][32]
    float* As = smem;                                   // 8192 floats
    float* Bs = smem + 8192;                            // 4096 floats
    uint32_t sA = (uint32_t)__cvta_generic_to_shared(As);
    uint32_t sB = (uint32_t)__cvta_generic_to_shared(Bs);

    int tid = threadIdx.x;
    int b = blockIdx.y;
    int m0 = blockIdx.x * 128;
    const float* aBase = adj + ((size_t)b * NN + m0) * NN;
    const float* zBase = g_zT + (size_t)b * 64 * NN;

    auto loadTile = [&](int kb, int buf) {
        int k0 = kb * 32;
#pragma unroll
        for (int i = 0; i < 4; i++) {                   // A: 128 rows x 128B
            int id = tid + i * 256;
            int row = id >> 3, seg = id & 7;
            const float* src = aBase + (size_t)row * NN + k0 + seg * 4;
            uint32_t dst = sA + buf * 16384u +
                           (uint32_t)((row * 32 + ((seg ^ (row & 7)) << 2)) << 2);
            asm volatile("cp.async.cg.shared.global [%0], [%1], 16;" :: "r"(dst), "l"(src));
        }
#pragma unroll
        for (int i = 0; i < 2; i++) {                   // B: 64 rows x 128B
            int id = tid + i * 256;
            int row = id >> 3, seg = id & 7;
            const float* src = zBase + (size_t)row * NN + k0 + seg * 4;
            uint32_t dst = sB + buf * 8192u +
                           (uint32_t)((row * 32 + ((seg ^ (row & 7)) << 2)) << 2);
            asm volatile("cp.async.cg.shared.global [%0], [%1], 16;" :: "r"(dst), "l"(src));
        }
    };

    float acc[2][4][4];
#pragma unroll
    for (int a = 0; a < 2; a++)
#pragma unroll
        for (int n = 0; n < 4; n++)
#pragma unroll
            for (int c = 0; c < 4; c++) acc[a][n][c] = 0.f;

    int warp = tid >> 5, lane = tid & 31;
    int wm = warp >> 1, wn = warp & 1;
    int g = lane >> 2, tg = lane & 3;

    loadTile(0, 0); asm volatile("cp.async.commit_group;");
    loadTile(1, 1); asm volatile("cp.async.commit_group;");

    for (int kb = 0; kb < 128; kb++) {
        asm volatile("cp.async.wait_group 1;");
        __syncthreads();
        int buf = kb & 1;
        const float* Ab = As + buf * 4096;
        const float* Bb = Bs + buf * 2048;
#pragma unroll
        for (int ks = 0; ks < 4; ks++) {
            uint32_t a[2][4], bf[4][2];
            int c0 = ks * 8 + tg, c1 = c0 + 4;
#pragma unroll
            for (int mt = 0; mt < 2; mt++) {
                int r = wm * 32 + mt * 16 + g;
                float f0 = Ab[r * 32       + (((c0 >> 2) ^ (r & 7)) << 2) + (c0 & 3)];
                float f1 = Ab[(r + 8) * 32 + (((c0 >> 2) ^ (r & 7)) << 2) + (c0 & 3)];
                float f2 = Ab[r * 32       + (((c1 >> 2) ^ (r & 7)) << 2) + (c1 & 3)];
                float f3 = Ab[(r + 8) * 32 + (((c1 >> 2) ^ (r & 7)) << 2) + (c1 & 3)];
                asm("cvt.rna.tf32.f32 %0, %1;" : "=r"(a[mt][0]) : "f"(f0));
                asm("cvt.rna.tf32.f32 %0, %1;" : "=r"(a[mt][1]) : "f"(f1));
                asm("cvt.rna.tf32.f32 %0, %1;" : "=r"(a[mt][2]) : "f"(f2));
                asm("cvt.rna.tf32.f32 %0, %1;" : "=r"(a[mt][3]) : "f"(f3));
            }
#pragma unroll
            for (int nt = 0; nt < 4; nt++) {
                int r = wn * 32 + nt * 8 + g;
                bf[nt][0] = __float_as_uint(Bb[r * 32 + (((c0 >> 2) ^ (r & 7)) << 2) + (c0 & 3)]);
                bf[nt][1] = __float_as_uint(Bb[r * 32 + (((c1 >> 2) ^ (r & 7)) << 2) + (c1 & 3)]);
            }
#pragma unroll
            for (int mt = 0; mt < 2; mt++)
#pragma unroll
                for (int nt = 0; nt < 4; nt++) {
                    asm volatile(
                        "mma.sync.aligned.m16n8k8.row.col.f32.tf32.tf32.f32 "
                        "{%0,%1,%2,%3}, {%4,%5,%6,%7}, {%8,%9}, {%0,%1,%2,%3};"
                        : "+f"(acc[mt][nt][0]), "+f"(acc[mt][nt][1]),
                          "+f"(acc[mt][nt][2]), "+f"(acc[mt][nt][3])
                        : "r"(a[mt][0]), "r"(a[mt][1]), "r"(a[mt][2]), "r"(a[mt][3]),
                          "r"(bf[nt][0]), "r"(bf[nt][1]));
                }
        }
        __syncthreads();
        if (kb + 2 < 128) loadTile(kb + 2, buf);
        asm volatile("cp.async.commit_group;");
    }

    // epilogue: relu(dis_n * acc + bias)
    float* hOut = g_h + ((size_t)b * NN + m0) * 64;
#pragma unroll
    for (int mt = 0; mt < 2; mt++) {
#pragma unroll
        for (int h2 = 0; h2 < 2; h2++) {
            int row = wm * 32 + mt * 16 + g + h2 * 8;
            float dv = g_dis[b * NN + m0 + row];
#pragma unroll
            for (int nt = 0; nt < 4; nt++) {
                int col = wn * 32 + nt * 8 + tg * 2;
                float v0 = fmaxf(dv * acc[mt][nt][2 * h2]     + bias[col],     0.f);
                float v1 = fmaxf(dv * acc[mt][nt][2 * h2 + 1] + bias[col + 1], 0.f);
                *reinterpret_cast<float2*>(hOut + (size_t)row * 64 + col) = make_float2(v0, v1);
            }
        }
    }
}

// ---------------- 4) pooling (partial over 128-node chunks) ----------------
__global__ void pool_partial() {
    int b = blockIdx.y, chunk = blockIdx.x;
    int t = threadIdx.x;
    int d = t & 63, grp = t >> 6;
    const float* hp = g_h + ((size_t)b * NN + chunk * 128 + grp * 32) * 64;
    float s = 0.f, mx = -1e30f;
#pragma unroll 4
    for (int i = 0; i < 32; i++) {
        float v = hp[(size_t)i * 64 + d];
        s += v; mx = fmaxf(mx, v);
    }
    __shared__ float ss[256], sm[256];
    ss[t] = s; sm[t] = mx;
    __syncthreads();
    if (t < 64) {
        float S = ss[t] + ss[t + 64] + ss[t + 128] + ss[t + 192];
        float M = fmaxf(fmaxf(sm[t], sm[t + 64]), fmaxf(sm[t + 128], sm[t + 192]));
        g_pool[((b * 32 + chunk) << 7) + t]      = S;
        g_pool[((b * 32 + chunk) << 7) + 64 + t] = M;
    }
}

// ---------------- 5) final combine + readout --------------------------------
__global__ void final_kernel(const float* __restrict__ Wr,
                             const float* __restrict__ br,
                             float* __restrict__ out) {
    int b = blockIdx.x, t = threadIdx.x;                // 128 threads
    __shared__ float pooled[128];
    if (t < 64) {
        float s = 0.f;
        for (int c = 0; c < 32; c++) s += g_pool[((b * 32 + c) << 7) + t];
        pooled[t] = s * (1.0f / 4096.0f);
    } else {
        float m = -1e30f;
        for (int c = 0; c < 32; c++) m = fmaxf(m, g_pool[((b * 32 + c) << 7) + t]);
        pooled[t] = m;
    }
    __syncthreads();
    if (t < 64) {
        float acc = br[t];
#pragma unroll
        for (int j = 0; j < 128; j++) acc += pooled[j] * Wr[t * 128 + j];
        out[b * 64 + t] = acc;
    }
}

// ---------------- launch -----------------------------------------------------
extern "C" void kernel_launch(void* const* d_in, const int* in_sizes, int n_in,
                              void* d_out, int out_size) {
    const int*   node_types  = (const int*)  d_in[0];
    const int*   node_labels = (const int*)  d_in[1];
    const float* adj         = (const float*)d_in[2];
    const float* type_emb    = (const float*)d_in[3];
    const float* label_emb   = (const float*)d_in[4];
    const float* W1          = (const float*)d_in[5];
    const float* b1          = (const float*)d_in[6];
    const float* W2          = (const float*)d_in[7];
    const float* b2          = (const float*)d_in[8];
    const float* Wr          = (const float*)d_in[9];
    const float* br          = (const float*)d_in[10];
    float* out = (float*)d_out;

    deg_kernel<<<BB * NN, 128>>>(adj);
    proj_kernel<<<BB * NN / 32, 256>>>(node_types, node_labels, type_emb, label_emb, 0, W1);
    gcn_gemm<<<dim3(NN / 128, BB), 256, 49152>>>(adj, b1);
    proj_kernel<<<BB * NN / 32, 256>>>(node_types, node_labels, type_emb, label_emb, 1, W2);
    gcn_gemm<<<dim3(NN / 128, BB), 256, 49152>>>(adj, b2);
    pool_partial<<<dim3(32, BB), 256>>>();
    final_kernel<<<BB, 128>>>(Wr, br, out);
}

// round 4
// speedup vs baseline: 1.5719x; 1.5719x over previous
#include <cuda_runtime.h>
#include <cuda_fp16.h>
#include <cstdint>

#define BB 16
#define NN 4096

// ---------------- scratch (device globals; no dynamic allocation) ----------
__device__ float g_dis[BB * NN];                            // 256 KB
__device__ __half g_adjh[(size_t)BB * NN * NN];             // 512 MB, dis[n]*adj
__device__ __half g_z1[(size_t)BB * 64 * NN];               // 8 MB  [b][d][m]
__device__ __half g_z2[(size_t)BB * 64 * NN];               // 8 MB
__device__ float g_pool[BB * 32 * 128];                     // pool partials

// ---------------- small PTX helpers ----------------------------------------
__device__ __forceinline__ void ldm4(uint32_t& r0, uint32_t& r1, uint32_t& r2,
                                     uint32_t& r3, uint32_t a) {
    asm volatile("ldmatrix.sync.aligned.m8n8.x4.shared.b16 {%0,%1,%2,%3}, [%4];"
                 : "=r"(r0), "=r"(r1), "=r"(r2), "=r"(r3) : "r"(a));
}
__device__ __forceinline__ void mma16816(float* d, const uint32_t* a, const uint32_t* b) {
    asm volatile(
        "mma.sync.aligned.m16n8k16.row.col.f32.f16.f16.f32 "
        "{%0,%1,%2,%3},{%4,%5,%6,%7},{%8,%9},{%0,%1,%2,%3};"
        : "+f"(d[0]), "+f"(d[1]), "+f"(d[2]), "+f"(d[3])
        : "r"(a[0]), "r"(a[1]), "r"(a[2]), "r"(a[3]), "r"(b[0]), "r"(b[1]));
}

// load W^T (64x64) into swizzled fp16 smem tile: ws[d][k] = W[k][d]
__device__ __forceinline__ void load_wT(const float* __restrict__ W, char* wsPtr, int tid) {
    for (int idx = tid; idx < 4096; idx += 256) {
        int d = idx & 63, k = idx >> 6;
        int chunk = k >> 3;
        int off = d * 128 + ((chunk ^ (d & 7)) << 4) + (k & 7) * 2;
        *(__half*)(wsPtr + off) = __float2half(W[k * 64 + d]);
    }
}

// mini MMA: [128x64 fp16 smem tile @xsA] x [64x64 W^T @wsA] -> zs[d][m] (pad 136)
__device__ __forceinline__ void mini_mma_store(uint32_t xsA, uint32_t wsA,
                                               __half* zs,
                                               int wm, int wn, int lane) {
    float acc[2][4][4];
#pragma unroll
    for (int mt = 0; mt < 2; mt++)
#pragma unroll
        for (int nt = 0; nt < 4; nt++)
#pragma unroll
            for (int c = 0; c < 4; c++) acc[mt][nt][c] = 0.f;

#pragma unroll
    for (int kt = 0; kt < 4; kt++) {
        uint32_t a[2][4], bb[4][2];
        int chunk = kt * 2 + (lane >> 4);
#pragma unroll
        for (int mt = 0; mt < 2; mt++) {
            int row = wm * 32 + mt * 16 + (lane & 15);
            ldm4(a[mt][0], a[mt][1], a[mt][2], a[mt][3],
                 xsA + row * 128 + ((chunk ^ (row & 7)) << 4));
        }
#pragma unroll
        for (int pr = 0; pr < 2; pr++) {
            int rn = wn * 32 + pr * 16 + (lane & 15);
            uint32_t r0, r1, r2, r3;
            ldm4(r0, r1, r2, r3, wsA + rn * 128 + ((chunk ^ (rn & 7)) << 4));
            bb[pr * 2][0] = r0; bb[pr * 2 + 1][0] = r1;
            bb[pr * 2][1] = r2; bb[pr * 2 + 1][1] = r3;
        }
#pragma unroll
        for (int mt = 0; mt < 2; mt++)
#pragma unroll
            for (int nt = 0; nt < 4; nt++) mma16816(acc[mt][nt], a[mt], bb[nt]);
    }
    int g = lane >> 2, t4 = lane & 3;
#pragma unroll
    for (int mt = 0; mt < 2; mt++)
#pragma unroll
        for (int nt = 0; nt < 4; nt++)
#pragma unroll
            for (int h2 = 0; h2 < 2; h2++) {
                int row = wm * 32 + mt * 16 + g + h2 * 8;
                int col = wn * 32 + nt * 8 + t4 * 2;
                zs[(size_t)col * 136 + row]       = __float2half(acc[mt][nt][h2 * 2]);
                zs[(size_t)(col + 1) * 136 + row] = __float2half(acc[mt][nt][h2 * 2 + 1]);
            }
}

// ---------------- 1) deg + dis + fp16 conversion (dis[n] folded) ------------
__global__ void conv_deg(const float* __restrict__ adj) {
    size_t row = blockIdx.x;
    int t = threadIdx.x;
    const float4* p = reinterpret_cast<const float4*>(adj + row * NN);
    float4 v[8];
#pragma unroll
    for (int i = 0; i < 8; i++) v[i] = p[t + i * 128];
    float s = 0.f;
#pragma unroll
    for (int i = 0; i < 8; i++) s += (v[i].x + v[i].y) + (v[i].z + v[i].w);
#pragma unroll
    for (int o = 16; o; o >>= 1) s += __shfl_xor_sync(0xffffffffu, s, o);
    __shared__ float ws[4];
    __shared__ float sdis;
    if ((t & 31) == 0) ws[t >> 5] = s;
    __syncthreads();
    if (t == 0) {
        float tot = ws[0] + ws[1] + ws[2] + ws[3];
        float dis = rsqrtf(fmaxf(tot, 1.0f));
        g_dis[row] = dis;
        sdis = dis;
    }
    __syncthreads();
    float d = sdis;
    uint2* orow = reinterpret_cast<uint2*>(g_adjh + row * NN);
#pragma unroll
    for (int i = 0; i < 8; i++) {
        __half2 lo = __floats2half2_rn(v[i].x * d, v[i].y * d);
        __half2 hi = __floats2half2_rn(v[i].z * d, v[i].w * d);
        uint2 o;
        o.x = *reinterpret_cast<uint32_t*>(&lo);
        o.y = *reinterpret_cast<uint32_t*>(&hi);
        orow[t + i * 128] = o;
    }
}

// ---------------- 2) proj1: z1[m][d] = dis[m]*(x[m] @ W1), fp16, transposed -
__global__ void __launch_bounds__(256) proj1_kernel(
    const int* __restrict__ ntypes, const int* __restrict__ nlabels,
    const float* __restrict__ te, const float* __restrict__ le,
    const float* __restrict__ W1) {
    __shared__ __align__(16) char sm[41984];   // xs 16K | ws 8K | zs 17408
    int tid = threadIdx.x;
    int base = blockIdx.x * 128;
    load_wT(W1, sm + 16384, tid);

    int node_l = tid >> 1, half = tid & 1;
    int node = base + node_l;
    const float* src = half ? (le + nlabels[node] * 32) : (te + ntypes[node] * 32);
    float dv = g_dis[node];
#pragma unroll
    for (int j = 0; j < 8; j++) {
        float4 v = reinterpret_cast<const float4*>(src)[j];
        __half2 p0 = __floats2half2_rn(v.x * dv, v.y * dv);
        __half2 p1 = __floats2half2_rn(v.z * dv, v.w * dv);
        int col = half * 32 + j * 4;
        int chunk = col >> 3;
        int off = node_l * 128 + ((chunk ^ (node_l & 7)) << 4) + (col & 7) * 2;
        uint2 u;
        u.x = *reinterpret_cast<uint32_t*>(&p0);
        u.y = *reinterpret_cast<uint32_t*>(&p1);
        *reinterpret_cast<uint2*>(sm + off) = u;
    }
    __syncthreads();

    int warp = tid >> 5, lane = tid & 31, wm = warp >> 1, wn = warp & 1;
    uint32_t sA = (uint32_t)__cvta_generic_to_shared(sm);
    __half* zs = reinterpret_cast<__half*>(sm + 24576);
    mini_mma_store(sA, sA + 16384, zs, wm, wn, lane);
    __syncthreads();

    int b = base >> 12, m0 = base & 4095;
    for (int idx = tid; idx < 4096; idx += 256) {
        int d = idx >> 6, cw = idx & 63;
        uint32_t v = *reinterpret_cast<uint32_t*>(zs + d * 136 + cw * 2);
        *reinterpret_cast<uint32_t*>(g_z1 + ((size_t)(b * 64 + d)) * NN + m0 + cw * 2) = v;
    }
}

// ---------------- 3) main GEMM --------------------------------------------
// mode 1: acc = adjh @ z1^T ; h = relu(acc + b1); z2 = dis[m]*(h @ W2) -> g_z2
// mode 2: acc = adjh @ z2^T ; h = relu(acc + b2); pool partials -> g_pool
__global__ void __launch_bounds__(256, 2) gcn_gemm(
    const float* __restrict__ bias, const float* __restrict__ Wnext, int mode) {
    extern __shared__ char sm[];
    int tid = threadIdx.x, b = blockIdx.y, m0 = blockIdx.x * 128;
    uint32_t sA = (uint32_t)__cvta_generic_to_shared(sm);
    uint32_t sB = sA + 32768;
    if (mode == 1) load_wT(Wnext, sm + 49152, tid);

    const __half* zin = (mode == 1) ? g_z1 : g_z2;
    const __half* aBase = g_adjh + ((size_t)b * NN + m0) * NN;
    const __half* zBase = zin + (size_t)b * 64 * NN;

    auto loadTile = [&](int kb, int buf) {
        int k0 = kb * 64;
#pragma unroll
        for (int i = 0; i < 4; i++) {
            int id = tid + i * 256;
            int row = id >> 3, c = id & 7;
            const void* src = aBase + (size_t)row * NN + k0 + c * 8;
            uint32_t dst = sA + buf * 16384 + row * 128 + ((c ^ (row & 7)) << 4);
            asm volatile("cp.async.cg.shared.global [%0],[%1],16;" :: "r"(dst), "l"(src));
        }
#pragma unroll
        for (int i = 0; i < 2; i++) {
            int id = tid + i * 256;
            int row = id >> 3, c = id & 7;
            const void* src = zBase + (size_t)row * NN + k0 + c * 8;
            uint32_t dst = sB + buf * 8192 + row * 128 + ((c ^ (row & 7)) << 4);
            asm volatile("cp.async.cg.shared.global [%0],[%1],16;" :: "r"(dst), "l"(src));
        }
    };

    float acc[2][4][4];
#pragma unroll
    for (int mt = 0; mt < 2; mt++)
#pragma unroll
        for (int nt = 0; nt < 4; nt++)
#pragma unroll
            for (int c = 0; c < 4; c++) acc[mt][nt][c] = 0.f;

    int warp = tid >> 5, lane = tid & 31, wm = warp >> 1, wn = warp & 1;

    loadTile(0, 0); asm volatile("cp.async.commit_group;");
    loadTile(1, 1); asm volatile("cp.async.commit_group;");

    for (int kb = 0; kb < 64; kb++) {
        asm volatile("cp.async.wait_group 1;");
        __syncthreads();
        int buf = kb & 1;
        uint32_t Ab = sA + buf * 16384, Bb = sB + buf * 8192;
#pragma unroll
        for (int kt = 0; kt < 4; kt++) {
            uint32_t a[2][4], bb[4][2];
            int chunk = kt * 2 + (lane >> 4);
#pragma unroll
            for (int mt = 0; mt < 2; mt++) {
                int row = wm * 32 + mt * 16 + (lane & 15);
                ldm4(a[mt][0], a[mt][1], a[mt][2], a[mt][3],
                     Ab + row * 128 + ((chunk ^ (row & 7)) << 4));
            }
#pragma unroll
            for (int pr = 0; pr < 2; pr++) {
                int rn = wn * 32 + pr * 16 + (lane & 15);
                uint32_t r0, r1, r2, r3;
                ldm4(r0, r1, r2, r3, Bb + rn * 128 + ((chunk ^ (rn & 7)) << 4));
                bb[pr * 2][0] = r0; bb[pr * 2 + 1][0] = r1;
                bb[pr * 2][1] = r2; bb[pr * 2 + 1][1] = r3;
            }
#pragma unroll
            for (int mt = 0; mt < 2; mt++)
#pragma unroll
                for (int nt = 0; nt < 4; nt++) mma16816(acc[mt][nt], a[mt], bb[nt]);
        }
        __syncthreads();
        if (kb + 2 < 64) loadTile(kb + 2, buf);
        asm volatile("cp.async.commit_group;");
    }
    asm volatile("cp.async.wait_group 0;");
    __syncthreads();

    int g = lane >> 2, t4 = lane & 3;
    if (mode == 1) {
        // stage h' = dis[m] * relu(acc + b1) as fp16 swizzled tile at sm[0]
#pragma unroll
        for (int mt = 0; mt < 2; mt++)
#pragma unroll
            for (int h2 = 0; h2 < 2; h2++) {
                int row = wm * 32 + mt * 16 + g + h2 * 8;
                float dv = g_dis[b * NN + m0 + row];
#pragma unroll
                for (int nt = 0; nt < 4; nt++) {
                    int col = wn * 32 + nt * 8 + t4 * 2;
                    float v0 = fmaxf(acc[mt][nt][h2 * 2]     + bias[col],     0.f) * dv;
                    float v1 = fmaxf(acc[mt][nt][h2 * 2 + 1] + bias[col + 1], 0.f) * dv;
                    int chunk = col >> 3;
                    int off = row * 128 + ((chunk ^ (row & 7)) << 4) + (col & 7) * 2;
                    __half2 p = __floats2half2_rn(v0, v1);
                    *reinterpret_cast<uint32_t*>(sm + off) = *reinterpret_cast<uint32_t*>(&p);
                }
            }
        __syncthreads();
        __half* zs = reinterpret_cast<__half*>(sm + 16384);
        mini_mma_store(sA, sA + 49152, zs, wm, wn, lane);
        __syncthreads();
        for (int idx = tid; idx < 4096; idx += 256) {
            int d = idx >> 6, cw = idx & 63;
            uint32_t v = *reinterpret_cast<uint32_t*>(zs + d * 136 + cw * 2);
            *reinterpret_cast<uint32_t*>(g_z2 + ((size_t)(b * 64 + d)) * NN + m0 + cw * 2) = v;
        }
    } else {
        // stage h = relu(acc + b2) fp32, then pool partials
        float* hs = reinterpret_cast<float*>(sm);
#pragma unroll
        for (int mt = 0; mt < 2; mt++)
#pragma unroll
            for (int h2 = 0; h2 < 2; h2++) {
                int row = wm * 32 + mt * 16 + g + h2 * 8;
#pragma unroll
                for (int nt = 0; nt < 4; nt++) {
                    int col = wn * 32 + nt * 8 + t4 * 2;
                    hs[row * 65 + col]     = fmaxf(acc[mt][nt][h2 * 2]     + bias[col],     0.f);
                    hs[row * 65 + col + 1] = fmaxf(acc[mt][nt][h2 * 2 + 1] + bias[col + 1], 0.f);
                }
            }
        __syncthreads();
        float* red = reinterpret_cast<float*>(sm + 33792);
        int d = tid & 63, part = tid >> 6;
        float s = 0.f, mx = -1e30f;
#pragma unroll 4
        for (int r = part * 32; r < part * 32 + 32; r++) {
            float v = hs[r * 65 + d];
            s += v; mx = fmaxf(mx, v);
        }
        red[tid] = s; red[256 + tid] = mx;
        __syncthreads();
        if (tid < 64) {
            float S = red[tid] + red[tid + 64] + red[tid + 128] + red[tid + 192];
            float M = fmaxf(fmaxf(red[256 + tid], red[256 + tid + 64]),
                            fmaxf(red[256 + tid + 128], red[256 + tid + 192]));
            g_pool[((b * 32 + blockIdx.x) << 7) + tid]      = S;
            g_pool[((b * 32 + blockIdx.x) << 7) + 64 + tid] = M;
        }
    }
}

// ---------------- 4) final combine + readout --------------------------------
__global__ void final_kernel(const float* __restrict__ Wr,
                             const float* __restrict__ br,
                             float* __restrict__ out) {
    int b = blockIdx.x, t = threadIdx.x;
    __shared__ float pooled[128];
    if (t < 64) {
        float s = 0.f;
        for (int c = 0; c < 32; c++) s += g_pool[((b * 32 + c) << 7) + t];
        pooled[t] = s * (1.0f / 4096.0f);
    } else {
        float m = -1e30f;
        for (int c = 0; c < 32; c++) m = fmaxf(m, g_pool[((b * 32 + c) << 7) + (t - 64) + 64]);
        pooled[t] = m;
    }
    __syncthreads();
    if (t < 64) {
        float acc = br[t];
#pragma unroll
        for (int j = 0; j < 128; j++) acc += pooled[j] * Wr[t * 128 + j];
        out[b * 64 + t] = acc;
    }
}

// ---------------- launch -----------------------------------------------------
extern "C" void kernel_launch(void* const* d_in, const int* in_sizes, int n_in,
                              void* d_out, int out_size) {
    const int*   node_types  = (const int*)  d_in[0];
    const int*   node_labels = (const int*)  d_in[1];
    const float* adj         = (const float*)d_in[2];
    const float* type_emb    = (const float*)d_in[3];
    const float* label_emb   = (const float*)d_in[4];
    const float* W1          = (const float*)d_in[5];
    const float* b1          = (const float*)d_in[6];
    const float* W2          = (const float*)d_in[7];
    const float* b2          = (const float*)d_in[8];
    const float* Wr          = (const float*)d_in[9];
    const float* br          = (const float*)d_in[10];
    float* out = (float*)d_out;

    cudaFuncSetAttribute(gcn_gemm, cudaFuncAttributeMaxDynamicSharedMemorySize, 57344);

    conv_deg<<<BB * NN, 128>>>(adj);
    proj1_kernel<<<BB * NN / 128, 256>>>(node_types, node_labels, type_emb, label_emb, W1);
    gcn_gemm<<<dim3(32, BB), 256, 57344>>>(b1, W2, 1);
    gcn_gemm<<<dim3(32, BB), 256, 57344>>>(b2, nullptr, 2);
    final_kernel<<<BB, 128>>>(Wr, br, out);
}

// round 5
// speedup vs baseline: 1.6106x; 1.0246x over previous
#include <cuda_runtime.h>
#include <cuda_fp16.h>
#include <cstdint>

#define BB 16
#define NN 4096

// ---------------- scratch (device globals; no dynamic allocation) ----------
__device__ float g_dis[BB * NN];                            // 256 KB
__device__ __half g_adjh[(size_t)BB * NN * NN];             // 512 MB, dis[n]*adj
__device__ __half g_z1[(size_t)BB * 64 * NN];               // 8 MB  [b][d][m]
__device__ __half g_z2[(size_t)BB * 64 * NN];               // 8 MB
__device__ float g_pool[BB * 32 * 128];                     // pool partials

// ---------------- small PTX helpers ----------------------------------------
__device__ __forceinline__ void ldm4(uint32_t& r0, uint32_t& r1, uint32_t& r2,
                                     uint32_t& r3, uint32_t a) {
    asm volatile("ldmatrix.sync.aligned.m8n8.x4.shared.b16 {%0,%1,%2,%3}, [%4];"
                 : "=r"(r0), "=r"(r1), "=r"(r2), "=r"(r3) : "r"(a));
}
__device__ __forceinline__ void mma16816(float* d, const uint32_t* a, const uint32_t* b) {
    asm volatile(
        "mma.sync.aligned.m16n8k16.row.col.f32.f16.f16.f32 "
        "{%0,%1,%2,%3},{%4,%5,%6,%7},{%8,%9},{%0,%1,%2,%3};"
        : "+f"(d[0]), "+f"(d[1]), "+f"(d[2]), "+f"(d[3])
        : "r"(a[0]), "r"(a[1]), "r"(a[2]), "r"(a[3]), "r"(b[0]), "r"(b[1]));
}

// load W^T (64x64) into swizzled fp16 smem tile: ws[d][k] = W[k][d]
__device__ __forceinline__ void load_wT(const float* __restrict__ W, char* wsPtr, int tid) {
    for (int idx = tid; idx < 4096; idx += 256) {
        int d = idx & 63, k = idx >> 6;
        int chunk = k >> 3;
        int off = d * 128 + ((chunk ^ (d & 7)) << 4) + (k & 7) * 2;
        *(__half*)(wsPtr + off) = __float2half(W[k * 64 + d]);
    }
}

// mini MMA: [128x64 fp16 smem tile @xsA] x [64x64 W^T @wsA] -> zs[d][m] (pad 136)
__device__ __forceinline__ void mini_mma_store(uint32_t xsA, uint32_t wsA,
                                               __half* zs,
                                               int wm, int wn, int lane) {
    float acc[2][4][4];
#pragma unroll
    for (int mt = 0; mt < 2; mt++)
#pragma unroll
        for (int nt = 0; nt < 4; nt++)
#pragma unroll
            for (int c = 0; c < 4; c++) acc[mt][nt][c] = 0.f;

#pragma unroll
    for (int kt = 0; kt < 4; kt++) {
        uint32_t a[2][4], bb[4][2];
        int chunk = kt * 2 + (lane >> 4);
#pragma unroll
        for (int mt = 0; mt < 2; mt++) {
            int row = wm * 32 + mt * 16 + (lane & 15);
            ldm4(a[mt][0], a[mt][1], a[mt][2], a[mt][3],
                 xsA + row * 128 + ((chunk ^ (row & 7)) << 4));
        }
#pragma unroll
        for (int pr = 0; pr < 2; pr++) {
            int rn = wn * 32 + pr * 16 + (lane & 15);
            uint32_t r0, r1, r2, r3;
            ldm4(r0, r1, r2, r3, wsA + rn * 128 + ((chunk ^ (rn & 7)) << 4));
            bb[pr * 2][0] = r0; bb[pr * 2 + 1][0] = r1;
            bb[pr * 2][1] = r2; bb[pr * 2 + 1][1] = r3;
        }
#pragma unroll
        for (int mt = 0; mt < 2; mt++)
#pragma unroll
            for (int nt = 0; nt < 4; nt++) mma16816(acc[mt][nt], a[mt], bb[nt]);
    }
    int g = lane >> 2, t4 = lane & 3;
#pragma unroll
    for (int mt = 0; mt < 2; mt++)
#pragma unroll
        for (int nt = 0; nt < 4; nt++)
#pragma unroll
            for (int h2 = 0; h2 < 2; h2++) {
                int row = wm * 32 + mt * 16 + g + h2 * 8;
                int col = wn * 32 + nt * 8 + t4 * 2;
                zs[(size_t)col * 136 + row]       = __float2half(acc[mt][nt][h2 * 2]);
                zs[(size_t)(col + 1) * 136 + row] = __float2half(acc[mt][nt][h2 * 2 + 1]);
            }
}

// ---------------- 1) deg + dis + fp16 conversion (dis[n] folded) ------------
__global__ void conv_deg(const float* __restrict__ adj) {
    size_t row = blockIdx.x;
    int t = threadIdx.x;
    const float4* p = reinterpret_cast<const float4*>(adj + row * NN);
    float4 v[8];
#pragma unroll
    for (int i = 0; i < 8; i++) v[i] = p[t + i * 128];
    float s = 0.f;
#pragma unroll
    for (int i = 0; i < 8; i++) s += (v[i].x + v[i].y) + (v[i].z + v[i].w);
#pragma unroll
    for (int o = 16; o; o >>= 1) s += __shfl_xor_sync(0xffffffffu, s, o);
    __shared__ float ws[4];
    __shared__ float sdis;
    if ((t & 31) == 0) ws[t >> 5] = s;
    __syncthreads();
    if (t == 0) {
        float tot = ws[0] + ws[1] + ws[2] + ws[3];
        float dis = rsqrtf(fmaxf(tot, 1.0f));
        g_dis[row] = dis;
        sdis = dis;
    }
    __syncthreads();
    float d = sdis;
    uint2* orow = reinterpret_cast<uint2*>(g_adjh + row * NN);
#pragma unroll
    for (int i = 0; i < 8; i++) {
        __half2 lo = __floats2half2_rn(v[i].x * d, v[i].y * d);
        __half2 hi = __floats2half2_rn(v[i].z * d, v[i].w * d);
        uint2 o;
        o.x = *reinterpret_cast<uint32_t*>(&lo);
        o.y = *reinterpret_cast<uint32_t*>(&hi);
        orow[t + i * 128] = o;
    }
}

// ---------------- 2) proj1: z1[m][d] = dis[m]*(x[m] @ W1), fp16, transposed -
__global__ void __launch_bounds__(256) proj1_kernel(
    const int* __restrict__ ntypes, const int* __restrict__ nlabels,
    const float* __restrict__ te, const float* __restrict__ le,
    const float* __restrict__ W1) {
    __shared__ __align__(16) char sm[41984];   // xs 16K | ws 8K | zs 17408
    int tid = threadIdx.x;
    int base = blockIdx.x * 128;
    load_wT(W1, sm + 16384, tid);

    int node_l = tid >> 1, half = tid & 1;
    int node = base + node_l;
    const float* src = half ? (le + nlabels[node] * 32) : (te + ntypes[node] * 32);
    float dv = g_dis[node];
#pragma unroll
    for (int j = 0; j < 8; j++) {
        float4 v = reinterpret_cast<const float4*>(src)[j];
        __half2 p0 = __floats2half2_rn(v.x * dv, v.y * dv);
        __half2 p1 = __floats2half2_rn(v.z * dv, v.w * dv);
        int col = half * 32 + j * 4;
        int chunk = col >> 3;
        int off = node_l * 128 + ((chunk ^ (node_l & 7)) << 4) + (col & 7) * 2;
        uint2 u;
        u.x = *reinterpret_cast<uint32_t*>(&p0);
        u.y = *reinterpret_cast<uint32_t*>(&p1);
        *reinterpret_cast<uint2*>(sm + off) = u;
    }
    __syncthreads();

    int warp = tid >> 5, lane = tid & 31, wm = warp >> 1, wn = warp & 1;
    uint32_t sA = (uint32_t)__cvta_generic_to_shared(sm);
    __half* zs = reinterpret_cast<__half*>(sm + 24576);
    mini_mma_store(sA, sA + 16384, zs, wm, wn, lane);
    __syncthreads();

    int b = base >> 12, m0 = base & 4095;
    for (int idx = tid; idx < 4096; idx += 256) {
        int d = idx >> 6, cw = idx & 63;
        uint32_t v = *reinterpret_cast<uint32_t*>(zs + d * 136 + cw * 2);
        *reinterpret_cast<uint32_t*>(g_z1 + ((size_t)(b * 64 + d)) * NN + m0 + cw * 2) = v;
    }
}

// ---------------- 3) main GEMM (4-stage cp.async pipeline) ------------------
// mode 1: acc = adjh @ z1^T ; h = relu(acc + b1); z2 = dis[m]*(h @ W2) -> g_z2
// mode 2: acc = adjh @ z2^T ; h = relu(acc + b2); pool partials -> g_pool
// smem layout: A stages [4][128][64]h @0 (64KB) | B stages [4][64][64]h @65536
//              (32KB) | W @98304 (8KB)  => 106496 bytes
__global__ void __launch_bounds__(256, 2) gcn_gemm(
    const float* __restrict__ bias, const float* __restrict__ Wnext, int mode) {
    extern __shared__ char sm[];
    int tid = threadIdx.x, b = blockIdx.y, m0 = blockIdx.x * 128;
    uint32_t sA = (uint32_t)__cvta_generic_to_shared(sm);
    uint32_t sB = sA + 65536;
    if (mode == 1) load_wT(Wnext, sm + 98304, tid);

    const __half* zin = (mode == 1) ? g_z1 : g_z2;
    const __half* aBase = g_adjh + ((size_t)b * NN + m0) * NN;
    const __half* zBase = zin + (size_t)b * 64 * NN;

    auto loadTile = [&](int kb, int buf) {
        int k0 = kb * 64;
#pragma unroll
        for (int i = 0; i < 4; i++) {
            int id = tid + i * 256;
            int row = id >> 3, c = id & 7;
            const void* src = aBase + (size_t)row * NN + k0 + c * 8;
            uint32_t dst = sA + buf * 16384 + row * 128 + ((c ^ (row & 7)) << 4);
            asm volatile("cp.async.cg.shared.global [%0],[%1],16;" :: "r"(dst), "l"(src));
        }
#pragma unroll
        for (int i = 0; i < 2; i++) {
            int id = tid + i * 256;
            int row = id >> 3, c = id & 7;
            const void* src = zBase + (size_t)row * NN + k0 + c * 8;
            uint32_t dst = sB + buf * 8192 + row * 128 + ((c ^ (row & 7)) << 4);
            asm volatile("cp.async.cg.shared.global [%0],[%1],16;" :: "r"(dst), "l"(src));
        }
    };

    float acc[2][4][4];
#pragma unroll
    for (int mt = 0; mt < 2; mt++)
#pragma unroll
        for (int nt = 0; nt < 4; nt++)
#pragma unroll
            for (int c = 0; c < 4; c++) acc[mt][nt][c] = 0.f;

    int warp = tid >> 5, lane = tid & 31, wm = warp >> 1, wn = warp & 1;

    loadTile(0, 0); asm volatile("cp.async.commit_group;");
    loadTile(1, 1); asm volatile("cp.async.commit_group;");
    loadTile(2, 2); asm volatile("cp.async.commit_group;");
    loadTile(3, 3); asm volatile("cp.async.commit_group;");

    for (int kb = 0; kb < 64; kb++) {
        asm volatile("cp.async.wait_group 3;");
        __syncthreads();
        int buf = kb & 3;
        uint32_t Ab = sA + buf * 16384, Bb = sB + buf * 8192;
#pragma unroll
        for (int kt = 0; kt < 4; kt++) {
            uint32_t a[2][4], bb[4][2];
            int chunk = kt * 2 + (lane >> 4);
#pragma unroll
            for (int mt = 0; mt < 2; mt++) {
                int row = wm * 32 + mt * 16 + (lane & 15);
                ldm4(a[mt][0], a[mt][1], a[mt][2], a[mt][3],
                     Ab + row * 128 + ((chunk ^ (row & 7)) << 4));
            }
#pragma unroll
            for (int pr = 0; pr < 2; pr++) {
                int rn = wn * 32 + pr * 16 + (lane & 15);
                uint32_t r0, r1, r2, r3;
                ldm4(r0, r1, r2, r3, Bb + rn * 128 + ((chunk ^ (rn & 7)) << 4));
                bb[pr * 2][0] = r0; bb[pr * 2 + 1][0] = r1;
                bb[pr * 2][1] = r2; bb[pr * 2 + 1][1] = r3;
            }
#pragma unroll
            for (int mt = 0; mt < 2; mt++)
#pragma unroll
                for (int nt = 0; nt < 4; nt++) mma16816(acc[mt][nt], a[mt], bb[nt]);
        }
        __syncthreads();
        if (kb + 4 < 64) loadTile(kb + 4, buf);
        asm volatile("cp.async.commit_group;");
    }
    asm volatile("cp.async.wait_group 0;");
    __syncthreads();

    int g = lane >> 2, t4 = lane & 3;
    if (mode == 1) {
        // stage h' = dis[m] * relu(acc + b1) as fp16 swizzled tile at sm[0]
#pragma unroll
        for (int mt = 0; mt < 2; mt++)
#pragma unroll
            for (int h2 = 0; h2 < 2; h2++) {
                int row = wm * 32 + mt * 16 + g + h2 * 8;
                float dv = g_dis[b * NN + m0 + row];
#pragma unroll
                for (int nt = 0; nt < 4; nt++) {
                    int col = wn * 32 + nt * 8 + t4 * 2;
                    float v0 = fmaxf(acc[mt][nt][h2 * 2]     + bias[col],     0.f) * dv;
                    float v1 = fmaxf(acc[mt][nt][h2 * 2 + 1] + bias[col + 1], 0.f) * dv;
                    int chunk = col >> 3;
                    int off = row * 128 + ((chunk ^ (row & 7)) << 4) + (col & 7) * 2;
                    __half2 p = __floats2half2_rn(v0, v1);
                    *reinterpret_cast<uint32_t*>(sm + off) = *reinterpret_cast<uint32_t*>(&p);
                }
            }
        __syncthreads();
        __half* zs = reinterpret_cast<__half*>(sm + 16384);
        mini_mma_store(sA, sA + 98304, zs, wm, wn, lane);
        __syncthreads();
        for (int idx = tid; idx < 4096; idx += 256) {
            int d = idx >> 6, cw = idx & 63;
            uint32_t v = *reinterpret_cast<uint32_t*>(zs + d * 136 + cw * 2);
            *reinterpret_cast<uint32_t*>(g_z2 + ((size_t)(b * 64 + d)) * NN + m0 + cw * 2) = v;
        }
    } else {
        // stage h = relu(acc + b2) fp32, then pool partials
        float* hs = reinterpret_cast<float*>(sm);
#pragma unroll
        for (int mt = 0; mt < 2; mt++)
#pragma unroll
            for (int h2 = 0; h2 < 2; h2++) {
                int row = wm * 32 + mt * 16 + g + h2 * 8;
#pragma unroll
                for (int nt = 0; nt < 4; nt++) {
                    int col = wn * 32 + nt * 8 + t4 * 2;
                    hs[row * 65 + col]     = fmaxf(acc[mt][nt][h2 * 2]     + bias[col],     0.f);
                    hs[row * 65 + col + 1] = fmaxf(acc[mt][nt][h2 * 2 + 1] + bias[col + 1], 0.f);
                }
            }
        __syncthreads();
        float* red = reinterpret_cast<float*>(sm + 33792);
        int d = tid & 63, part = tid >> 6;
        float s = 0.f, mx = -1e30f;
#pragma unroll 4
        for (int r = part * 32; r < part * 32 + 32; r++) {
            float v = hs[r * 65 + d];
            s += v; mx = fmaxf(mx, v);
        }
        red[tid] = s; red[256 + tid] = mx;
        __syncthreads();
        if (tid < 64) {
            float S = red[tid] + red[tid + 64] + red[tid + 128] + red[tid + 192];
            float M = fmaxf(fmaxf(red[256 + tid], red[256 + tid + 64]),
                            fmaxf(red[256 + tid + 128], red[256 + tid + 192]));
            g_pool[((b * 32 + blockIdx.x) << 7) + tid]      = S;
            g_pool[((b * 32 + blockIdx.x) << 7) + 64 + tid] = M;
        }
    }
}

// ---------------- 4) final combine + readout --------------------------------
__global__ void final_kernel(const float* __restrict__ Wr,
                             const float* __restrict__ br,
                             float* __restrict__ out) {
    int b = blockIdx.x, t = threadIdx.x;
    __shared__ float pooled[128];
    if (t < 64) {
        float s = 0.f;
        for (int c = 0; c < 32; c++) s += g_pool[((b * 32 + c) << 7) + t];
        pooled[t] = s * (1.0f / 4096.0f);
    } else {
        float m = -1e30f;
        for (int c = 0; c < 32; c++) m = fmaxf(m, g_pool[((b * 32 + c) << 7) + (t - 64) + 64]);
        pooled[t] = m;
    }
    __syncthreads();
    if (t < 64) {
        float acc = br[t];
#pragma unroll
        for (int j = 0; j < 128; j++) acc += pooled[j] * Wr[t * 128 + j];
        out[b * 64 + t] = acc;
    }
}

// ---------------- launch -----------------------------------------------------
extern "C" void kernel_launch(void* const* d_in, const int* in_sizes, int n_in,
                              void* d_out, int out_size) {
    const int*   node_types  = (const int*)  d_in[0];
    const int*   node_labels = (const int*)  d_in[1];
    const float* adj         = (const float*)d_in[2];
    const float* type_emb    = (const float*)d_in[3];
    const float* label_emb   = (const float*)d_in[4];
    const float* W1          = (const float*)d_in[5];
    const float* b1          = (const float*)d_in[6];
    const float* W2          = (const float*)d_in[7];
    const float* b2          = (const float*)d_in[8];
    const float* Wr          = (const float*)d_in[9];
    const float* br          = (const float*)d_in[10];
    float* out = (float*)d_out;

    cudaFuncSetAttribute(gcn_gemm, cudaFuncAttributeMaxDynamicSharedMemorySize, 106496);

    conv_deg<<<BB * NN, 128>>>(adj);
    proj1_kernel<<<BB * NN / 128, 256>>>(node_types, node_labels, type_emb, label_emb, W1);
    gcn_gemm<<<dim3(32, BB), 256, 106496>>>(b1, W2, 1);
    gcn_gemm<<<dim3(32, BB), 256, 106496>>>(b2, nullptr, 2);
    final_kernel<<<BB, 128>>>(Wr, br, out);
}